// round 2
// baseline (speedup 1.0000x reference)
#include <cuda_runtime.h>
#include <math_constants.h>

#define BATCH 32
#define NN 1024
#define MM 1024
#define FF 4
#define LL (NN + MM - 1)   // 2047

// Scratch (static device allocations are allowed; cudaMalloc is not)
__device__ unsigned char g_moves[(size_t)BATCH * LL * NN];   // 67 MB, L2-resident working set per phase
__device__ float g_loss[BATCH];

// ---------------------------------------------------------------------------
// Phase 1: DTW forward DP, anti-diagonal wavefront. One CTA per batch,
// thread i owns row i. Double-buffered diagonals in shared memory; one
// __syncthreads per diagonal. Records argmin move per cell (coalesced bytes).
// ---------------------------------------------------------------------------
__global__ __launch_bounds__(NN, 1)
void dtw_dp_kernel(const float* __restrict__ preds,
                   const float* __restrict__ targs)
{
    const int b = blockIdx.x;
    const int i = threadIdx.x;

    __shared__ float2 s_t[MM];       // targ basis coords (x,y)
    __shared__ float  s_d[2][NN];    // double-buffered diagonals

    const float* pb = preds + (size_t)b * NN * FF;
    const float* tb = targs + (size_t)b * MM * FF;

    // targ coords -> shared (each thread loads one)
    float2 tcoord;
    tcoord.x = tb[i * FF + 0];
    tcoord.y = tb[i * FF + 1];
    s_t[i] = tcoord;

    // pred coords for my row -> registers
    const float px = pb[i * FF + 0];
    const float py = pb[i * FF + 1];

    unsigned char* mv = g_moves + (size_t)b * LL * NN;

    const float INF = CUDART_INF_F;
    s_d[1][i] = INF;                 // "diagonal -1" buffer
    float my_prev   = INF;           // D[i][j-1]   (my value on diag k-1)
    float left_prev = INF;           // D[i-1][j-1] (left-neighbor value on diag k-2)

    __syncthreads();

    #pragma unroll 1
    for (int k = 0; k < LL; ++k) {
        const int  j     = k - i;
        const bool valid = (j >= 0) && (j < MM);
        const int  jc    = min(max(j, 0), MM - 1);

        const float2 t  = s_t[jc];
        const float  dx = px - t.x;
        const float  dy = py - t.y;
        const float  c  = sqrtf(dx * dx + dy * dy);

        // up = D[i-1][j] from diag k-1 (buffer (k-1)&1 == (k+1)&1)
        const float up = (i > 0) ? s_d[(k + 1) & 1][i - 1] : INF;
        const float dg = left_prev;   // D[i-1][j-1]
        const float lf = my_prev;     // D[i][j-1]

        float best = fminf(fminf(up, dg), lf);
        const float bestc = isinf(best) ? 0.0f : best;  // (0,0) seed
        const float cur = valid ? (c + bestc) : INF;

        // argmin over [dg, up, lf], first-wins ties (matches jnp.argmin order)
        int   m  = 0;
        float bv = dg;
        if (up < bv) { m = 1; bv = up; }
        if (lf < bv) { m = 2; }

        s_d[k & 1][i] = cur;
        mv[(size_t)k * NN + i] = (unsigned char)m;   // coalesced byte store

        my_prev   = cur;
        left_prev = up;
        __syncthreads();
    }
}

// ---------------------------------------------------------------------------
// Phase 2: backtrack + loss accumulation. One thread per batch (serial chase).
// Moves are L2-resident from phase 1.
// ---------------------------------------------------------------------------
__global__ void dtw_bt_kernel(const float* __restrict__ preds,
                              const float* __restrict__ targs,
                              const float* __restrict__ subcoef)
{
    const int b = blockIdx.x;
    if (threadIdx.x != 0) return;

    const float sc0 = subcoef[0];
    const float sc1 = subcoef[1];

    const unsigned char* mv = g_moves + (size_t)b * LL * NN;
    const float* pb = preds + (size_t)b * NN * FF;
    const float* tb = targs + (size_t)b * MM * FF;

    int i = NN - 1;
    int j = MM - 1;
    float loss = 0.0f;

    #pragma unroll 1
    while (true) {
        const float p0 = pb[i * FF + 0];
        const float p1 = pb[i * FF + 1];
        const float t0 = tb[j * FF + 0];
        const float t1 = tb[j * FF + 1];
        loss += fabsf(p0 - t0) * sc0 + fabsf(p1 - t1) * sc1;

        if ((i == 0) && (j == 0)) break;

        const int m = mv[(size_t)(i + j) * NN + i];
        const int ni = (m == 2) ? i : i - 1;
        const int nj = (m == 1) ? j : j - 1;
        i = ni;
        j = nj;
    }

    g_loss[b] = loss;
}

// ---------------------------------------------------------------------------
// Phase 3: fixed-order reduction (deterministic; no fp atomics).
// ---------------------------------------------------------------------------
__global__ void dtw_sum_kernel(float* __restrict__ out)
{
    if (threadIdx.x == 0 && blockIdx.x == 0) {
        float s = 0.0f;
        #pragma unroll
        for (int b = 0; b < BATCH; ++b) s += g_loss[b];
        out[0] = s;
    }
}

extern "C" void kernel_launch(void* const* d_in, const int* in_sizes, int n_in,
                              void* d_out, int out_size)
{
    const float* preds   = (const float*)d_in[0];
    const float* targs   = (const float*)d_in[1];
    const float* subcoef = (const float*)d_in[2];
    float* out = (float*)d_out;

    dtw_dp_kernel<<<BATCH, NN>>>(preds, targs);
    dtw_bt_kernel<<<BATCH, 32>>>(preds, targs, subcoef);
    dtw_sum_kernel<<<1, 32>>>(out);
}

// round 3
// speedup vs baseline: 1.0840x; 1.0840x over previous
#include <cuda_runtime.h>
#include <math_constants.h>

#define BATCH 32
#define NN 1024
#define MM 1024
#define FF 4
#define LL (NN + MM - 1)          // 2047
#define NWORDS (NN / 32)          // 32 move-words per diagonal
#define WD 256                    // backtrack window: diagonals
#define WS 9                      // backtrack window: strips
#define CANARY 0xFFC00000u        // negative-NaN bit pattern (DP values are finite >= 0)

// 2-bit moves packed as ballot pairs: [batch][diag k][strip s] -> uint2 {bit0, bit1}
// 32 * 2047 * 32 * 8 B = 16.8 MB  -> L2-resident
__device__ uint2 g_mv[(size_t)BATCH * LL * NWORDS];
__device__ float g_loss[BATCH];

// Dynamic shared layout:
//   [0      .. 8704)   float2 s_t[1088]   targ coords, padded +32 both sides
//   [8704   .. 16896)  float2 s_p[1024]   pred coords
//   [16896  .. )       phase A: float bnd[31][1024] (126976 B)  |  union with
//                      phase B: uint2 sh_win[WD*WS] (18432) + int sh_path[2048] (8192)
//                               + float s_red[32] + int s_ctl[4]
#define SMEM_TOTAL (16896 + 31 * 1024 * 4)

__global__ __launch_bounds__(1024, 1)
void dtw_fused_kernel(const float* __restrict__ preds,
                      const float* __restrict__ targs,
                      const float* __restrict__ subcoef)
{
    extern __shared__ char smem[];
    float2* s_t = (float2*)smem;                   // index with j+32
    float2* s_p = (float2*)(smem + 8704);
    char*   dyn = smem + 16896;

    const int b    = blockIdx.x;
    const int tid  = threadIdx.x;
    const int warp = tid >> 5;
    const int lane = tid & 31;
    const float INF = CUDART_INF_F;

    const float* pb = preds + (size_t)b * NN * FF;
    const float* tb = targs + (size_t)b * MM * FF;

    // ---- stage coords ----
    float4 p4 = ((const float4*)pb)[tid];
    const float px = p4.x, py = p4.y;
    s_p[tid] = make_float2(px, py);
    float4 t4 = ((const float4*)tb)[tid];
    s_t[tid + 32] = make_float2(t4.x, t4.y);
    if (tid < 32) { s_t[tid] = make_float2(0.f, 0.f); s_t[1056 + tid] = make_float2(0.f, 0.f); }

    // ---- init cross-warp boundary buffer to canary ----
    unsigned* bnd_u = (unsigned*)dyn;              // 31*1024 words
    for (int idx = tid; idx < 31 * 1024; idx += 1024) bnd_u[idx] = CANARY;
    __syncthreads();

    // =====================================================================
    // Phase A: warp-pipelined DTW forward DP.
    // Warp s owns rows [32s, 32s+32); lane r owns row i = 32s + r.
    // At local step t, lane r computes cell (i, j = t - r); global diag k = 32s + t.
    //   left = own prev; up = shfl_up(prev); diag = previous step's up.
    //   lane0's `up` comes from the strip above via NaN-canary spin in shared.
    // =====================================================================
    {
        volatile unsigned* bnd_rd = (warp > 0) ? bnd_u + (warp - 1) * 1024 : bnd_u;
        volatile unsigned* bnd_wr = bnd_u + warp * 1024;  // used only if warp < 31

        uint2* mvp = g_mv + ((size_t)b * LL + warp * 32) * NWORDS + warp;

        float prev = INF;   // D[i][j-1]
        float dg   = INF;   // D[i-1][j-1]
        int   j    = -lane;

        #pragma unroll 1
        for (int t = 0; t < NN + 31; ++t, ++j) {
            float up = __shfl_up_sync(0xffffffffu, prev, 1);
            if (lane == 0) {
                up = INF;
                if (warp > 0 && (unsigned)j < (unsigned)MM) {
                    unsigned uv = bnd_rd[j];
                    while (uv == CANARY) uv = bnd_rd[j];
                    up = __uint_as_float(uv);
                }
            }

            const float2 tc = s_t[j + 32];
            const float dx = px - tc.x;
            const float dy = py - tc.y;
            const float c  = sqrtf(dx * dx + dy * dy);

            const float best  = fminf(fminf(up, dg), prev);
            // argmin over [diag, up, left], first-wins ties (matches jnp.argmin)
            int   m  = 0;
            float bv = dg;
            if (up   < bv) { m = 1; bv = up; }
            if (prev < bv) { m = 2; }

            const float bestc = (best == INF) ? 0.0f : best;   // (0,0) seed
            const bool  valid = (unsigned)j < (unsigned)MM;
            const float cur   = valid ? (c + bestc) : INF;

            const unsigned b0 = __ballot_sync(0xffffffffu, m & 1);
            const unsigned b1 = __ballot_sync(0xffffffffu, m >> 1);
            if (lane == 0) mvp[(size_t)t * NWORDS] = make_uint2(b0, b1);

            if (lane == 31 && warp < 31 && valid) bnd_wr[j] = __float_as_uint(cur);

            dg   = up;
            prev = cur;
        }
    }
    __syncthreads();   // bnd region is dead; reuse for phase B

    // =====================================================================
    // Phase B: windowed backtrack (moves staged to shared) + parallel loss.
    // =====================================================================
    uint2* sh_win  = (uint2*)dyn;                          // WD*WS = 2304 words
    int*   sh_path = (int*)(dyn + WD * WS * 8);            // 2048 ints
    float* s_red   = (float*)(dyn + WD * WS * 8 + 8192);   // 32 floats
    int*   s_ctl   = (int*)(dyn + WD * WS * 8 + 8192 + 128);

    if (tid == 0) { s_ctl[0] = LL - 1; s_ctl[1] = NN - 1; s_ctl[2] = 0; s_ctl[3] = 0; }
    __syncthreads();

    #pragma unroll 1
    while (true) {
        const int k0 = s_ctl[0], i0 = s_ctl[1], done = s_ctl[3];
        if (done) break;

        const int klo  = max(0, k0 - (WD - 1));
        const int smin = max(0, (i0 - WD) >> 5);

        // cooperative window stage (MLP-rich, L2 hits)
        for (int idx = tid; idx < WD * WS; idx += 1024) {
            const int kk = klo + idx / WS;
            const int ss = smin + idx % WS;
            uint2 w = make_uint2(0u, 0u);
            if (kk < LL && ss < NWORDS)
                w = g_mv[((size_t)b * LL + kk) * NWORDS + ss];
            sh_win[idx] = w;
        }
        __syncthreads();

        if (tid == 0) {
            int k = k0, i = i0, len = s_ctl[2];
            #pragma unroll 1
            while (k >= klo) {
                sh_path[len++] = (i << 11) | (k - i);
                if (k == 0) { s_ctl[3] = 1; break; }   // reached (0,0)
                const uint2 w = sh_win[(k - klo) * WS + ((i >> 5) - smin)];
                const int r = i & 31;
                const int m = ((w.x >> r) & 1) | (((w.y >> r) & 1) << 1);
                i -= (m == 2) ? 0 : 1;                 // left keeps i
                k -= (m == 0) ? 2 : 1;                 // diag skips a diagonal
            }
            s_ctl[0] = k; s_ctl[1] = i; s_ctl[2] = len;
        }
        __syncthreads();
    }

    // ---- parallel loss over the recorded path ----
    const int len = s_ctl[2];
    const float sc0 = subcoef[0];
    const float sc1 = subcoef[1];

    float acc = 0.0f;
    for (int e = tid; e < len; e += 1024) {
        const int p  = sh_path[e];
        const int pi = p >> 11;
        const int pj = p & 2047;
        const float2 pp = s_p[pi];
        const float2 tt = s_t[pj + 32];
        acc += fabsf(pp.x - tt.x) * sc0 + fabsf(pp.y - tt.y) * sc1;
    }
    #pragma unroll
    for (int o = 16; o > 0; o >>= 1) acc += __shfl_down_sync(0xffffffffu, acc, o);
    if (lane == 0) s_red[warp] = acc;
    __syncthreads();
    if (warp == 0) {
        float v = s_red[lane];
        #pragma unroll
        for (int o = 16; o > 0; o >>= 1) v += __shfl_down_sync(0xffffffffu, v, o);
        if (lane == 0) g_loss[b] = v;
    }
}

// Fixed-order deterministic reduction across batches.
__global__ void dtw_sum_kernel(float* __restrict__ out)
{
    if (threadIdx.x == 0 && blockIdx.x == 0) {
        float s = 0.0f;
        #pragma unroll
        for (int b = 0; b < BATCH; ++b) s += g_loss[b];
        out[0] = s;
    }
}

extern "C" void kernel_launch(void* const* d_in, const int* in_sizes, int n_in,
                              void* d_out, int out_size)
{
    const float* preds   = (const float*)d_in[0];
    const float* targs   = (const float*)d_in[1];
    const float* subcoef = (const float*)d_in[2];
    float* out = (float*)d_out;

    cudaFuncSetAttribute(dtw_fused_kernel,
                         cudaFuncAttributeMaxDynamicSharedMemorySize, SMEM_TOTAL);

    dtw_fused_kernel<<<BATCH, 1024, SMEM_TOTAL>>>(preds, targs, subcoef);
    dtw_sum_kernel<<<1, 32>>>(out);
}

// round 5
// speedup vs baseline: 1.3352x; 1.2318x over previous
#include <cuda_runtime.h>
#include <math_constants.h>

#define BATCH 32
#define NN 1024
#define MM 1024
#define FF 4
#define STRIPS 16                 // 64 rows per strip
#define ROWS_PER_STRIP 64
#define NCHUNK 33                 // steps t in [0, 1056), covers t_max = 1054
#define TDIM (NCHUNK * 32)        // 1056
#define FULLM 0xffffffffu

// moves: per (batch, strip, step t) one uint4 of 4 ballots:
//   {m0 bit0, m0 bit1, m1 bit0, m1 bit1} over 32 lanes (lane r owns rows 2r, 2r+1)
__device__ uint4 g_mv[(size_t)BATCH * STRIPS * TDIM];            // 8.7 MB
__device__ float g_bnd[(size_t)BATCH * STRIPS * MM];             // bottom-row D values
__device__ int   g_flag[BATCH * STRIPS * 32];                    // chunk-ready flags
__device__ float g_loss[BATCH];

// ---------------------------------------------------------------------------
// Phase 0: zero handoff flags (must precede DP every invocation)
// ---------------------------------------------------------------------------
__global__ void dtw_init_kernel()
{
    g_flag[blockIdx.x * 512 + threadIdx.x] = 0;
}

// ---------------------------------------------------------------------------
// Phase 1: DTW forward DP. One WARP per (batch, strip). Lane r owns rows
// 2r, 2r+1 of the strip; at local step t it computes column j = t - r for
// both rows. Intra-warp: shfl. Inter-strip: global bnd[] values + chunked
// release/acquire flags (poll once per 32 steps).
// ---------------------------------------------------------------------------
__global__ __launch_bounds__(32, 32)
void dtw_dp_kernel(const float* __restrict__ preds,
                   const float* __restrict__ targs)
{
    const int bid = blockIdx.x;          // bid = s * BATCH + b  (producers first)
    const int b   = bid & (BATCH - 1);
    const int s   = bid / BATCH;
    const int r   = threadIdx.x;

    __shared__ float2 s_t[MM];

    const float* tb = targs + (size_t)b * MM * FF;
    #pragma unroll 4
    for (int i = r; i < MM; i += 32) {
        // load only (x, y) of each targ row
        s_t[i] = ((const float2*)tb)[2 * i];
    }
    __syncwarp();

    const float* pb = preds + (size_t)b * NN * FF;
    const int row0 = s * ROWS_PER_STRIP + 2 * r;
    const float2 pa = ((const float2*)pb)[2 * row0];
    const float2 pc = ((const float2*)pb)[2 * (row0 + 1)];
    const float px0 = pa.x, py0 = pa.y, px1 = pc.x, py1 = pc.y;

    float*       bnd_wr  = g_bnd + ((size_t)b * STRIPS + s) * MM;
    const float* bnd_rd  = g_bnd + ((size_t)b * STRIPS + (s - 1)) * MM;
    volatile int* flag_rd = g_flag + (b * STRIPS + (s - 1)) * 32;
    volatile int* flag_wr = g_flag + (b * STRIPS + s) * 32;
    uint4* mv = g_mv + (size_t)(b * STRIPS + s) * TDIM;

    const float INF = CUDART_INF_F;
    float prev0 = INF;    // D[row0][j-1]
    float prev1 = INF;    // D[row0+1][j-1]
    float c1prev = INF;   // my cur1 from previous step (for neighbor's shfl)
    float dg0 = INF;      // D[row0-1][j-1]
    float bndreg = INF;   // boundary chunk value held by this lane

    #pragma unroll 1
    for (int c = 0; c < NCHUNK; ++c) {
        if (s > 0 && c < 32) {
            if (r == 0) { while (flag_rd[c] == 0) { } }
            __syncwarp();
            __threadfence();                       // acquire
            bndreg = bnd_rd[c * 32 + r];
        }

        #pragma unroll 8
        for (int tt = 0; tt < 32; ++tt) {
            const int t = c * 32 + tt;
            const int j = t - r;
            const bool valid = (unsigned)j < (unsigned)MM;

            // neighbor's bottom-row value D[row0-1][j]
            const float sh     = __shfl_up_sync(FULLM, c1prev, 1);
            const float bv_bnd = __shfl_sync(FULLM, bndreg, tt);
            const float up0 = (r == 0) ? ((s > 0) ? bv_bnd : INF) : sh;

            float2 tc = valid ? s_t[j] : make_float2(0.f, 0.f);
            const float dx0 = px0 - tc.x, dy0 = py0 - tc.y;
            const float c0 = sqrtf(dx0 * dx0 + dy0 * dy0);
            const float dx1 = px1 - tc.x, dy1 = py1 - tc.y;
            const float c1 = sqrtf(dx1 * dx1 + dy1 * dy1);

            // cell 0: cand order [dg, up, left] for argmin (first-wins ties)
            const float e0    = fminf(dg0, prev0);
            const float best0 = fminf(up0, e0);
            const float cur0  = valid ? (c0 + (best0 == INF ? 0.f : best0)) : INF;
            int m0 = 0;
            { float bv = dg0; if (up0 < bv) { m0 = 1; bv = up0; } if (prev0 < bv) m0 = 2; }

            // cell 1: up = cur0, dg = prev0, left = prev1
            const float e1    = fminf(prev0, prev1);
            const float best1 = fminf(cur0, e1);
            const float cur1  = valid ? (c1 + (best1 == INF ? 0.f : best1)) : INF;
            int m1 = 0;
            { float bv = prev0; if (cur0 < bv) { m1 = 1; bv = cur0; } if (prev1 < bv) m1 = 2; }

            const unsigned a0 = __ballot_sync(FULLM, m0 & 1);
            const unsigned a1 = __ballot_sync(FULLM, m0 >> 1);
            const unsigned a2 = __ballot_sync(FULLM, m1 & 1);
            const unsigned a3 = __ballot_sync(FULLM, m1 >> 1);
            if (r == 0) mv[t] = make_uint4(a0, a1, a2, a3);

            if (r == 31 && s < STRIPS - 1 && valid) bnd_wr[j] = cur1;

            dg0 = up0; prev0 = cur0; prev1 = cur1; c1prev = cur1;
        }

        // after inner chunk c, bnd columns [0, 32c] are written -> publish chunk c-1
        if (s < STRIPS - 1 && c >= 1) {
            __syncwarp();
            if (r == 31) { __threadfence(); flag_wr[c - 1] = 1; }   // release
        }
    }
}

// ---------------------------------------------------------------------------
// Phase 2: windowed backtrack + parallel loss. One CTA per batch.
// ---------------------------------------------------------------------------
__global__ __launch_bounds__(1024, 1)
void dtw_bt_kernel(const float* __restrict__ preds,
                   const float* __restrict__ targs,
                   const float* __restrict__ subcoef)
{
    __shared__ float2 s_p[NN];
    __shared__ float2 s_t[MM];
    __shared__ uint4  s_win[5 * 288];      // <=5 strips x 288 step-words
    __shared__ int    s_path[2048];
    __shared__ float  s_red[32];
    __shared__ int    s_ctl[4];            // i, j, len, done

    const int b    = blockIdx.x;
    const int tid  = threadIdx.x;
    const int warp = tid >> 5;
    const int lane = tid & 31;

    const float* pb = preds + (size_t)b * NN * FF;
    const float* tb = targs + (size_t)b * MM * FF;
    s_p[tid] = ((const float2*)pb)[2 * tid];
    s_t[tid] = ((const float2*)tb)[2 * tid];

    if (tid == 0) { s_ctl[0] = NN - 1; s_ctl[1] = MM - 1; s_ctl[2] = 0; s_ctl[3] = 0; }
    __syncthreads();

    #pragma unroll 1
    while (s_ctl[3] == 0) {
        const int i0 = s_ctl[0], j0 = s_ctl[1];
        const int slo = max(0, i0 - 255) >> 6;
        const int shi = i0 >> 6;
        const int nst = shi - slo + 1;
        const int jlo = max(0, j0 - 255);
        const int tlo = jlo;
        __syncthreads();

        // stage window: strips [slo, shi], steps [tlo, tlo+288)
        const int nw = nst * 288;
        for (int idx = tid; idx < nw; idx += 1024) {
            const int ss = slo + idx / 288;
            const int t  = tlo + idx % 288;
            uint4 w = make_uint4(0u, 0u, 0u, 0u);
            if (t < TDIM) w = g_mv[(size_t)(b * STRIPS + ss) * TDIM + t];
            s_win[idx] = w;
        }
        __syncthreads();

        if (tid == 0) {
            int i = i0, j = j0, len = s_ctl[2], done = 0;
            const int ilim = slo * 64;
            #pragma unroll 1
            while (i >= ilim && j >= jlo) {
                s_path[len++] = (i << 11) | j;
                if ((i | j) == 0) { done = 1; break; }
                const int li = i & 63;
                const int rr = li >> 1;
                const uint4 w = s_win[((i >> 6) - slo) * 288 + (j + rr - tlo)];
                const unsigned lo = (li & 1) ? w.z : w.x;
                const unsigned hi = (li & 1) ? w.w : w.y;
                const int m = ((lo >> rr) & 1) | (((hi >> rr) & 1) << 1);
                i -= (m == 2) ? 0 : 1;
                j -= (m == 1) ? 0 : 1;
            }
            s_ctl[0] = i; s_ctl[1] = j; s_ctl[2] = len; s_ctl[3] = done;
        }
        __syncthreads();
    }

    // parallel loss over recorded path, deterministic reduction
    const int len = s_ctl[2];
    const float sc0 = subcoef[0];
    const float sc1 = subcoef[1];

    float acc = 0.0f;
    for (int e = tid; e < len; e += 1024) {
        const int p  = s_path[e];
        const int pi = p >> 11;
        const int pj = p & 2047;
        const float2 pp = s_p[pi];
        const float2 tt = s_t[pj];
        acc += fabsf(pp.x - tt.x) * sc0 + fabsf(pp.y - tt.y) * sc1;
    }
    #pragma unroll
    for (int o = 16; o > 0; o >>= 1) acc += __shfl_down_sync(FULLM, acc, o);
    if (lane == 0) s_red[warp] = acc;
    __syncthreads();
    if (warp == 0) {
        float v = s_red[lane];
        #pragma unroll
        for (int o = 16; o > 0; o >>= 1) v += __shfl_down_sync(FULLM, v, o);
        if (lane == 0) g_loss[b] = v;
    }
}

// ---------------------------------------------------------------------------
// Phase 3: fixed-order deterministic batch reduction
// ---------------------------------------------------------------------------
__global__ void dtw_sum_kernel(float* __restrict__ out)
{
    if (threadIdx.x == 0 && blockIdx.x == 0) {
        float su = 0.0f;
        #pragma unroll
        for (int b = 0; b < BATCH; ++b) su += g_loss[b];
        out[0] = su;
    }
}

extern "C" void kernel_launch(void* const* d_in, const int* in_sizes, int n_in,
                              void* d_out, int out_size)
{
    const float* preds   = (const float*)d_in[0];
    const float* targs   = (const float*)d_in[1];
    const float* subcoef = (const float*)d_in[2];
    float* out = (float*)d_out;

    dtw_init_kernel<<<BATCH, 512>>>();                     // zero flags
    dtw_dp_kernel<<<BATCH * STRIPS, 32>>>(preds, targs);   // 512 single-warp CTAs
    dtw_bt_kernel<<<BATCH, 1024>>>(preds, targs, subcoef);
    dtw_sum_kernel<<<1, 32>>>(out);
}